// round 6
// baseline (speedup 1.0000x reference)
#include <cuda_runtime.h>
#include <math.h>

#define NLEVELS 16
#define TBL     (1u << 19)
#define NPTS    (64 * 64 * 64)
#define NBINS   (1 << 15)          // 15-bit Morton key, 32 bins/axis

constexpr double SCALE_ = 1.447269237440378;

__host__ __device__ constexpr int res_of(int l) {
    double r = 16.0;
    for (int i = 0; i < l; ++i) r *= SCALE_;
    return (int)(r + 1e-6);
}

// ---- scratch (static device globals; no runtime allocation) ----
__device__ float g_sorted[NPTS * 3];
__device__ int   g_perm[NPTS];
__device__ int   g_keys[NPTS];
__device__ int   g_hist[NBINS];
__device__ int   g_cursor[NBINS];

__device__ __forceinline__ unsigned expand3(unsigned v) {
    // 5 bits -> bits 0,3,6,9,12
    return (v & 1u) | ((v & 2u) << 2) | ((v & 4u) << 4) |
           ((v & 8u) << 6) | ((v & 16u) << 8);
}

__global__ void k_zero_hist() {
    const int i = blockIdx.x * blockDim.x + threadIdx.x;
    if (i < NBINS) g_hist[i] = 0;
}

__global__ void k_keys_hist(const float* __restrict__ pts) {
    const int i = blockIdx.x * blockDim.x + threadIdx.x;
    if (i >= NPTS) return;
    const float x = pts[3 * i + 0];
    const float y = pts[3 * i + 1];
    const float z = pts[3 * i + 2];
    const unsigned ix = min(31, (int)(x * 32.f));
    const unsigned iy = min(31, (int)(y * 32.f));
    const unsigned iz = min(31, (int)(z * 32.f));
    const int key = (int)(expand3(ix) | (expand3(iy) << 1) | (expand3(iz) << 2));
    g_keys[i] = key;
    atomicAdd(&g_hist[key], 1);
}

__global__ __launch_bounds__(1024)
void k_scan() {
    __shared__ int warpsums[32];
    const int t = threadIdx.x;
    const int base = t * 32;
    int loc[32];
    int s = 0;
#pragma unroll
    for (int k = 0; k < 32; ++k) { loc[k] = s; s += g_hist[base + k]; }
    const int lane = t & 31, wid = t >> 5;
    int v = s;
#pragma unroll
    for (int o = 1; o < 32; o <<= 1) {
        const int n = __shfl_up_sync(~0u, v, o);
        if (lane >= o) v += n;
    }
    if (lane == 31) warpsums[wid] = v;
    __syncthreads();
    if (wid == 0) {
        int w = warpsums[lane];
#pragma unroll
        for (int o = 1; o < 32; o <<= 1) {
            const int n = __shfl_up_sync(~0u, w, o);
            if (lane >= o) w += n;
        }
        warpsums[lane] = w;
    }
    __syncthreads();
    const int excl = v - s + (wid ? warpsums[wid - 1] : 0);
#pragma unroll
    for (int k = 0; k < 32; ++k) g_cursor[base + k] = excl + loc[k];
}

__global__ void k_scatter(const float* __restrict__ pts) {
    const int i = blockIdx.x * blockDim.x + threadIdx.x;
    if (i >= NPTS) return;
    const int key = g_keys[i];
    const int pos = atomicAdd(&g_cursor[key], 1);
    g_perm[pos] = i;
    g_sorted[3 * pos + 0] = pts[3 * i + 0];
    g_sorted[3 * pos + 1] = pts[3 * i + 1];
    g_sorted[3 * pos + 2] = pts[3 * i + 2];
}

__global__ __launch_bounds__(256, 4)
void hashgrid_mlp_kernel(const float* __restrict__ table,
                         const float* __restrict__ w1,
                         const float* __restrict__ w2,
                         float* __restrict__ out)
{
    __shared__ float sw1[64 * 32];
    __shared__ float sw2[64];

    const int tid = threadIdx.x;
    for (int k = tid; k < 64 * 32; k += 256) sw1[k] = w1[k];
    if (tid < 64) sw2[tid] = w2[tid];
    __syncthreads();

    const int i = blockIdx.x * 256 + tid;

    const float px = g_sorted[3 * i + 0];
    const float py = g_sorted[3 * i + 1];
    const float pz = g_sorted[3 * i + 2];

    float enc[32];

    constexpr int RESA[NLEVELS] = {
        res_of(0),  res_of(1),  res_of(2),  res_of(3),
        res_of(4),  res_of(5),  res_of(6),  res_of(7),
        res_of(8),  res_of(9),  res_of(10), res_of(11),
        res_of(12), res_of(13), res_of(14), res_of(15)
    };

#pragma unroll
    for (int l = 0; l < NLEVELS; ++l) {
        const int res = RESA[l];
        const bool dense = ((long long)(res + 1) * (res + 1) * (res + 1) <= (long long)TBL);

        const float fres = (float)res;
        const float x = px * fres, y = py * fres, z = pz * fres;
        const float fx = floorf(x), fy = floorf(y), fz = floorf(z);
        const float tx = x - fx, ty = y - fy, tz = z - fz;
        const unsigned cx = (unsigned)fx, cy = (unsigned)fy, cz = (unsigned)fz;

        const float2* tab = (const float2*)table + (size_t)l * TBL;

        // 4 X-pairs: corners (cx,Y,Z) and (cx+1,Y,Z) for the 4 (Y,Z) combos.
        unsigned iA[4], iB[4];
#pragma unroll
        for (int c = 0; c < 4; ++c) {
            const unsigned Y = cy + ((c >> 1) & 1u);
            const unsigned Z = cz + (c & 1u);
            if (dense) {
                const unsigned r1 = (unsigned)(res + 1);
                const unsigned b = r1 * (Y + r1 * Z);
                iA[c] = (cx + b) & (TBL - 1u);
                iB[c] = (cx + 1u + b) & (TBL - 1u);
            } else {
                const unsigned h = (Y * 2654435761u) ^ (Z * 805459861u);
                iA[c] = (cx ^ h) & (TBL - 1u);
                iB[c] = ((cx + 1u) ^ h) & (TBL - 1u);
            }
        }

        float4 v[4];
#pragma unroll
        for (int c = 0; c < 4; ++c)
            v[c] = __ldg((const float4*)tab + (iA[c] >> 1));

        float2 b64[4];
        bool cont[4];
#pragma unroll
        for (int c = 0; c < 4; ++c) {
            cont[c] = ((iA[c] >> 1) == (iB[c] >> 1));
            if (!cont[c]) b64[c] = __ldg(tab + iB[c]);
        }

        float e0 = 0.f, e1 = 0.f;
#pragma unroll
        for (int c = 0; c < 4; ++c) {
            const float2 lo = make_float2(v[c].x, v[c].y);
            const float2 hi = make_float2(v[c].z, v[c].w);
            const float2 tA = (iA[c] & 1u) ? hi : lo;
            const float2 tBc = (iB[c] & 1u) ? hi : lo;
            const float2 tB = cont[c] ? tBc : b64[c];
            const float wyz = (((c >> 1) & 1) ? ty : 1.f - ty) *
                              ((c & 1) ? tz : 1.f - tz);
            const float wA = (1.f - tx) * wyz;
            const float wB = tx * wyz;
            e0 = fmaf(wA, tA.x, fmaf(wB, tB.x, e0));
            e1 = fmaf(wA, tA.y, fmaf(wB, tB.y, e1));
        }
        enc[2 * l + 0] = e0;
        enc[2 * l + 1] = e1;
    }

    // ---- tiny MLP ----
    float acc = 0.f;
#pragma unroll
    for (int j = 0; j < 64; ++j) {
        float h = 0.f;
        const float4* row = (const float4*)(sw1 + j * 32);
#pragma unroll
        for (int k = 0; k < 8; ++k) {
            const float4 v = row[k];
            h = fmaf(enc[4 * k + 0], v.x, h);
            h = fmaf(enc[4 * k + 1], v.y, h);
            h = fmaf(enc[4 * k + 2], v.z, h);
            h = fmaf(enc[4 * k + 3], v.w, h);
        }
        h = fmaxf(h, 0.f);
        acc = fmaf(h, sw2[j], acc);
    }

    out[g_perm[i]] = 1.f / (1.f + expf(-acc));
}

extern "C" void kernel_launch(void* const* d_in, const int* in_sizes, int n_in,
                              void* d_out, int out_size)
{
    const float* pts   = (const float*)d_in[0];   // [N,3]
    const float* table = (const float*)d_in[1];   // [16, 2^19, 2]
    const float* w1    = (const float*)d_in[2];   // [64, 32]
    const float* w2    = (const float*)d_in[3];   // [1, 64]
    float* out = (float*)d_out;

    k_zero_hist<<<NBINS / 256, 256>>>();
    k_keys_hist<<<NPTS / 256, 256>>>(pts);
    k_scan<<<1, 1024>>>();
    k_scatter<<<NPTS / 256, 256>>>(pts);
    hashgrid_mlp_kernel<<<NPTS / 256, 256>>>(table, w1, w2, out);
}

// round 7
// speedup vs baseline: 1.2598x; 1.2598x over previous
#include <cuda_runtime.h>
#include <math.h>

#define NLEVELS 16
#define TBL     (1u << 19)
#define NPTS    (64 * 64 * 64)

constexpr double SCALE_ = 1.447269237440378;

__host__ __device__ constexpr int res_of(int l) {
    double r = 16.0;
    for (int i = 0; i < l; ++i) r *= SCALE_;
    return (int)(r + 1e-6);
}

// MLP weights in constant memory: warp-uniform reads go through the uniform
// constant port (LDCU), not the L1tex pipe.
__constant__ float c_w1[64 * 32];
__constant__ float c_w2[64];

__global__ __launch_bounds__(256, 4)
void hashgrid_mlp_kernel(const float* __restrict__ pts,
                         const float* __restrict__ table,
                         float* __restrict__ out)
{
    const int i = blockIdx.x * 256 + threadIdx.x;

    const float px = __ldg(pts + 3 * i + 0);
    const float py = __ldg(pts + 3 * i + 1);
    const float pz = __ldg(pts + 3 * i + 2);

    float enc[32];

    constexpr int RESA[NLEVELS] = {
        res_of(0),  res_of(1),  res_of(2),  res_of(3),
        res_of(4),  res_of(5),  res_of(6),  res_of(7),
        res_of(8),  res_of(9),  res_of(10), res_of(11),
        res_of(12), res_of(13), res_of(14), res_of(15)
    };

#pragma unroll
    for (int l = 0; l < NLEVELS; ++l) {
        const int res = RESA[l];
        const bool dense = ((long long)(res + 1) * (res + 1) * (res + 1) <= (long long)TBL);

        const float fres = (float)res;
        const float x = px * fres, y = py * fres, z = pz * fres;
        const float fx = floorf(x), fy = floorf(y), fz = floorf(z);
        const float tx = x - fx, ty = y - fy, tz = z - fz;
        const unsigned cx = (unsigned)fx, cy = (unsigned)fy, cz = (unsigned)fz;

        const float2* tab = (const float2*)table + (size_t)l * TBL;

        // 4 X-pairs: corners (cx,Y,Z) and (cx+1,Y,Z) for the 4 (Y,Z) combos.
        unsigned iA[4], iB[4];
#pragma unroll
        for (int c = 0; c < 4; ++c) {
            const unsigned Y = cy + ((c >> 1) & 1u);
            const unsigned Z = cz + (c & 1u);
            if (dense) {
                const unsigned r1 = (unsigned)(res + 1);
                const unsigned b = r1 * (Y + r1 * Z);
                iA[c] = (cx + b) & (TBL - 1u);
                iB[c] = (cx + 1u + b) & (TBL - 1u);
            } else {
                const unsigned h = (Y * 2654435761u) ^ (Z * 805459861u);
                iA[c] = (cx ^ h) & (TBL - 1u);
                iB[c] = ((cx + 1u) ^ h) & (TBL - 1u);
            }
        }

        // Aligned 16B block holding iA (delivers iB too when pair contained).
        float4 v[4];
#pragma unroll
        for (int c = 0; c < 4; ++c)
            v[c] = __ldg((const float4*)tab + (iA[c] >> 1));

        float2 b64[4];
        bool cont[4];
#pragma unroll
        for (int c = 0; c < 4; ++c) {
            cont[c] = ((iA[c] >> 1) == (iB[c] >> 1));
            if (!cont[c]) b64[c] = __ldg(tab + iB[c]);
        }

        float e0 = 0.f, e1 = 0.f;
#pragma unroll
        for (int c = 0; c < 4; ++c) {
            const float2 lo = make_float2(v[c].x, v[c].y);
            const float2 hi = make_float2(v[c].z, v[c].w);
            const float2 tA = (iA[c] & 1u) ? hi : lo;
            const float2 tBc = (iB[c] & 1u) ? hi : lo;
            const float2 tB = cont[c] ? tBc : b64[c];
            const float wyz = (((c >> 1) & 1) ? ty : 1.f - ty) *
                              ((c & 1) ? tz : 1.f - tz);
            const float wA = (1.f - tx) * wyz;
            const float wB = tx * wyz;
            e0 = fmaf(wA, tA.x, fmaf(wB, tB.x, e0));
            e1 = fmaf(wA, tA.y, fmaf(wB, tB.y, e1));
        }
        enc[2 * l + 0] = e0;
        enc[2 * l + 1] = e1;
    }

    // ---- tiny MLP: weights from constant bank (uniform port, no L1tex) ----
    float acc = 0.f;
#pragma unroll
    for (int j = 0; j < 64; ++j) {
        float h = 0.f;
#pragma unroll
        for (int k = 0; k < 32; ++k)
            h = fmaf(enc[k], c_w1[j * 32 + k], h);
        h = fmaxf(h, 0.f);
        acc = fmaf(h, c_w2[j], acc);
    }

    out[i] = 1.f / (1.f + expf(-acc));
}

extern "C" void kernel_launch(void* const* d_in, const int* in_sizes, int n_in,
                              void* d_out, int out_size)
{
    const float* pts   = (const float*)d_in[0];   // [N,3]
    const float* table = (const float*)d_in[1];   // [16, 2^19, 2]
    const float* w1    = (const float*)d_in[2];   // [64, 32]
    const float* w2    = (const float*)d_in[3];   // [1, 64]
    float* out = (float*)d_out;

    cudaMemcpyToSymbolAsync(c_w1, w1, 64 * 32 * sizeof(float), 0,
                            cudaMemcpyDeviceToDevice);
    cudaMemcpyToSymbolAsync(c_w2, w2, 64 * sizeof(float), 0,
                            cudaMemcpyDeviceToDevice);

    hashgrid_mlp_kernel<<<NPTS / 256, 256>>>(pts, table, out);
}

// round 8
// speedup vs baseline: 1.4908x; 1.1833x over previous
#include <cuda_runtime.h>
#include <cuda_bf16.h>
#include <math.h>

#define NLEVELS 16
#define TBL     (1u << 19)
#define NPTS    (64 * 64 * 64)

constexpr double SCALE_ = 1.447269237440378;

__host__ __device__ constexpr int res_of(int l) {
    double r = 16.0;
    for (int i = 0; i < l; ++i) r *= SCALE_;
    return (int)(r + 1e-6);
}

__global__ __launch_bounds__(256, 4)
void hashgrid_mlp_kernel(const float* __restrict__ pts,
                         const float* __restrict__ table,
                         const float* __restrict__ w1,
                         const float* __restrict__ w2,
                         float* __restrict__ out)
{
    // w1 packed as bf16x2: row j has 16 entries pairing (k, k+1).
    __shared__ __nv_bfloat162 sw1p[64 * 16];
    __shared__ float sw2[64];

    const int tid = threadIdx.x;
    for (int k = tid; k < 64 * 16; k += 256)
        sw1p[k] = __floats2bfloat162_rn(w1[2 * k], w1[2 * k + 1]);
    if (tid < 64) sw2[tid] = w2[tid];
    __syncthreads();

    const int i = blockIdx.x * 256 + tid;

    const float px = __ldg(pts + 3 * i + 0);
    const float py = __ldg(pts + 3 * i + 1);
    const float pz = __ldg(pts + 3 * i + 2);

    __nv_bfloat162 enc2[NLEVELS];

    constexpr int RESA[NLEVELS] = {
        res_of(0),  res_of(1),  res_of(2),  res_of(3),
        res_of(4),  res_of(5),  res_of(6),  res_of(7),
        res_of(8),  res_of(9),  res_of(10), res_of(11),
        res_of(12), res_of(13), res_of(14), res_of(15)
    };

#pragma unroll
    for (int l = 0; l < NLEVELS; ++l) {
        const int res = RESA[l];
        const bool dense = ((long long)(res + 1) * (res + 1) * (res + 1) <= (long long)TBL);

        const float fres = (float)res;
        const float x = px * fres, y = py * fres, z = pz * fres;
        const float fx = floorf(x), fy = floorf(y), fz = floorf(z);
        const float tx = x - fx, ty = y - fy, tz = z - fz;
        const unsigned cx = (unsigned)fx, cy = (unsigned)fy, cz = (unsigned)fz;

        const float2* tab = (const float2*)table + (size_t)l * TBL;

        // 4 X-pairs: corners (cx,Y,Z) and (cx+1,Y,Z) for the 4 (Y,Z) combos.
        unsigned iA[4], iB[4];
#pragma unroll
        for (int c = 0; c < 4; ++c) {
            const unsigned Y = cy + ((c >> 1) & 1u);
            const unsigned Z = cz + (c & 1u);
            if (dense) {
                const unsigned r1 = (unsigned)(res + 1);
                const unsigned b = r1 * (Y + r1 * Z);
                iA[c] = (cx + b) & (TBL - 1u);
                iB[c] = (cx + 1u + b) & (TBL - 1u);
            } else {
                const unsigned h = (Y * 2654435761u) ^ (Z * 805459861u);
                iA[c] = (cx ^ h) & (TBL - 1u);
                iB[c] = ((cx + 1u) ^ h) & (TBL - 1u);
            }
        }

        // Aligned 16B block holding iA (delivers iB too when pair contained).
        float4 v[4];
#pragma unroll
        for (int c = 0; c < 4; ++c)
            v[c] = __ldg((const float4*)tab + (iA[c] >> 1));

        float2 b64[4];
        bool cont[4];
#pragma unroll
        for (int c = 0; c < 4; ++c) {
            cont[c] = ((iA[c] >> 1) == (iB[c] >> 1));
            if (!cont[c]) b64[c] = __ldg(tab + iB[c]);
        }

        float e0 = 0.f, e1 = 0.f;
#pragma unroll
        for (int c = 0; c < 4; ++c) {
            const float2 lo = make_float2(v[c].x, v[c].y);
            const float2 hi = make_float2(v[c].z, v[c].w);
            const float2 tA = (iA[c] & 1u) ? hi : lo;
            const float2 tBc = (iB[c] & 1u) ? hi : lo;
            const float2 tB = cont[c] ? tBc : b64[c];
            const float wyz = (((c >> 1) & 1) ? ty : 1.f - ty) *
                              ((c & 1) ? tz : 1.f - tz);
            const float wA = (1.f - tx) * wyz;
            const float wB = tx * wyz;
            e0 = fmaf(wA, tA.x, fmaf(wB, tB.x, e0));
            e1 = fmaf(wA, tA.y, fmaf(wB, tB.y, e1));
        }
        enc2[l] = __floats2bfloat162_rn(e0, e1);
    }

    // ---- tiny MLP in bf16x2: 4 LDS.128 + 16 HFMA2 per hidden unit ----
    float acc = 0.f;
#pragma unroll
    for (int j = 0; j < 64; ++j) {
        __nv_bfloat162 hacc = __floats2bfloat162_rn(0.f, 0.f);
        const float4* row = (const float4*)(sw1p + j * 16);
#pragma unroll
        for (int q = 0; q < 4; ++q) {
            float4 vf = row[q];
            const __nv_bfloat162 w0 = *reinterpret_cast<const __nv_bfloat162*>(&vf.x);
            const __nv_bfloat162 w1b = *reinterpret_cast<const __nv_bfloat162*>(&vf.y);
            const __nv_bfloat162 w2b = *reinterpret_cast<const __nv_bfloat162*>(&vf.z);
            const __nv_bfloat162 w3b = *reinterpret_cast<const __nv_bfloat162*>(&vf.w);
            hacc = __hfma2(enc2[4 * q + 0], w0, hacc);
            hacc = __hfma2(enc2[4 * q + 1], w1b, hacc);
            hacc = __hfma2(enc2[4 * q + 2], w2b, hacc);
            hacc = __hfma2(enc2[4 * q + 3], w3b, hacc);
        }
        float h = __low2float(hacc) + __high2float(hacc);
        h = fmaxf(h, 0.f);
        acc = fmaf(h, sw2[j], acc);
    }

    out[i] = __fdividef(1.f, 1.f + __expf(-acc));
}

extern "C" void kernel_launch(void* const* d_in, const int* in_sizes, int n_in,
                              void* d_out, int out_size)
{
    const float* pts   = (const float*)d_in[0];   // [N,3]
    const float* table = (const float*)d_in[1];   // [16, 2^19, 2]
    const float* w1    = (const float*)d_in[2];   // [64, 32]
    const float* w2    = (const float*)d_in[3];   // [1, 64]
    float* out = (float*)d_out;

    hashgrid_mlp_kernel<<<NPTS / 256, 256>>>(pts, table, w1, w2, out);
}